// round 9
// baseline (speedup 1.0000x reference)
#include <cuda_runtime.h>
#include <cuda_bf16.h>
#include <stdint.h>
#include <math.h>

// Problem constants
#define BN 8
#define CN 256
#define ON 256
#define HN 64
#define WN 64
#define HW 4096
#define K2 9
#define DGN 4
#define CGN 64
#define KD 2304          // CN*K2 (GEMM reduction dim)
#define GN_GROUPS 32
#define GRP_ELEMS 32768
#define EPS 1e-5f

// GEMM tiling (128x128, 512 threads, 16 warps as 4m x 4n; per-warp 32x32)
#define BM 128
#define BNT 128
#define BK 32
#define NCH (KD / BK)        // 72
#define ROWB 80              // padded SMEM row stride (bytes) for 32 bf16
#define T_A (BM * ROWB)      // 10240
#define T_B (BNT * ROWB)     // 10240
#define STAGE_B (2 * T_A + 2 * T_B)   // 40960
#define NSTAGE 3
#define GEMM_SMEM (NSTAGE * STAGE_B)  // 122880

// ---------------------------------------------------------------------------
// Device scratch
// ---------------------------------------------------------------------------
__device__ __nv_bfloat16 g_colh[(size_t)BN * HW * KD];   // [b][hw][kd]
__device__ __nv_bfloat16 g_coll[(size_t)BN * HW * KD];
__device__ __nv_bfloat16 g_wh[(size_t)ON * KD];
__device__ __nv_bfloat16 g_wl[(size_t)ON * KD];
__device__ float g_mu[BN * GN_GROUPS];
__device__ float g_rstd[BN * GN_GROUPS];

// ---------------------------------------------------------------------------
// PTX helpers (stable sm_80+ features only)
// ---------------------------------------------------------------------------
__device__ __forceinline__ uint32_t smem_u32(const void* p) {
    uint32_t a;
    asm("{ .reg .u64 t; cvta.to.shared.u64 t, %1; cvt.u32.u64 %0, t; }"
        : "=r"(a) : "l"(p));
    return a;
}
__device__ __forceinline__ void cp16(uint32_t s, const void* g) {
    asm volatile("cp.async.cg.shared.global [%0], [%1], 16;"
                 :: "r"(s), "l"(g) : "memory");
}
#define CP_COMMIT() asm volatile("cp.async.commit_group;" ::: "memory")
#define CP_WAIT(n)  asm volatile("cp.async.wait_group %0;" :: "n"(n) : "memory")

__device__ __forceinline__ void ldm_x4(uint32_t* r, uint32_t addr) {
    asm volatile("ldmatrix.sync.aligned.m8n8.x4.shared.b16 {%0,%1,%2,%3}, [%4];"
                 : "=r"(r[0]), "=r"(r[1]), "=r"(r[2]), "=r"(r[3]) : "r"(addr));
}
__device__ __forceinline__ void mma_bf16(float* c, const uint32_t* a,
                                         const uint32_t* b) {
    asm volatile(
        "mma.sync.aligned.m16n8k16.row.col.f32.bf16.bf16.f32 "
        "{%0,%1,%2,%3}, {%4,%5,%6,%7}, {%8,%9}, {%0,%1,%2,%3};"
        : "+f"(c[0]), "+f"(c[1]), "+f"(c[2]), "+f"(c[3])
        : "r"(a[0]), "r"(a[1]), "r"(a[2]), "r"(a[3]), "r"(b[0]), "r"(b[1]));
}

// ---------------------------------------------------------------------------
// Kernel A: split weights into bf16 hi/lo.
// ---------------------------------------------------------------------------
__global__ void wsplit_kernel(const float* __restrict__ w)
{
    int i = blockIdx.x * blockDim.x + threadIdx.x;
    float v = w[i];
    __nv_bfloat16 h = __float2bfloat16(v);
    __nv_bfloat16 l = __float2bfloat16(v - __bfloat162float(h));
    g_wh[i] = h;
    g_wl[i] = l;
}

// ---------------------------------------------------------------------------
// Kernel B (v4): deformable im2col with x-tile cached in SMEM.
// Block = (b, g, 16 consecutive hw = one row segment). The 5x20 spatial
// neighborhood of the segment is staged in SMEM for all 64 group channels;
// bilinear corners read SMEM when in-tile (nearly always; offsets are tiny),
// else fall back to a global load. Math and output layout identical to the
// validated v3: col[b][hw][kd], kd = g*576 + c*9 + k, bf16 hi/lo.
// ---------------------------------------------------------------------------
#define V4HW 16
#define TR 5                 // tile rows
#define TC 20                // tile cols
#define CSTRIDE 101          // padded floats per channel (5*20 -> 101, odd)
#define QP   288
#define SROW 289
#define IM2_SMEM (64 * CSTRIDE * 4 + 4 * 144 * 4 + 4 * 144 * 4 + \
                  2 * (V4HW * SROW * 4))        // 67456 B

__global__ void __launch_bounds__(256)
im2col4_kernel(const float* __restrict__ x,
               const float* __restrict__ x_off,
               const float* __restrict__ w_offset)
{
    const int b   = blockIdx.z;
    const int g   = blockIdx.y;
    const int hw0 = blockIdx.x * V4HW;
    const int tid = threadIdx.x;
    const int h   = hw0 >> 6;
    const int w0  = hw0 & 63;

    extern __shared__ char sm4[];
    float*    s_x = (float*)sm4;                         // 64*CSTRIDE
    int*      s_i = (int*)(s_x + 64 * CSTRIDE);          // 4*144
    float*    s_w = (float*)(s_i + 4 * 144);             // 4*144
    uint32_t* s_h = (uint32_t*)(s_w + 4 * 144);          // 16*SROW
    uint32_t* s_l = s_h + V4HW * SROW;                   // 16*SROW

    const float* xg = x + ((size_t)(b * CN + g * CGN)) * HW;

    // Load x tile: rows h-2..h+2, cols w0-2..w0+17, all 64 channels.
    for (int idx = tid; idx < 64 * TR * TC; idx += 256) {
        int c  = idx / (TR * TC);
        int rc = idx - c * (TR * TC);
        int r  = rc / TC;
        int cl = rc - r * TC;
        int y  = h - 2 + r;
        int xc = w0 - 2 + cl;
        if (y >= 0 && y < HN && xc >= 0 && xc < WN)
            s_x[c * CSTRIDE + rc] = xg[(size_t)c * HW + y * WN + xc];
    }

    // Phase 1: bilinear params for 16 hw x 9 k (validated math) + tile encode.
    if (tid < V4HW * 9) {
        int p   = tid;
        int hwl = p / 9;
        int k   = p - hwl * 9;
        int hw  = hw0 + hwl;
        int hh = hw >> 6, ww = hw & 63;

        const float* xo = x_off + (size_t)b * 4 * HW + hw;
        float o0 = xo[0], o1 = xo[HW], o2 = xo[2 * HW], o3 = xo[3 * HW];
        const float* wo = w_offset + (size_t)((g * K2 + k) * 2) * 4;
        float offy = wo[0] * o0 + wo[1] * o1 + wo[2] * o2 + wo[3] * o3;
        float offx = wo[4] * o0 + wo[5] * o1 + wo[6] * o2 + wo[7] * o3;

        float py = (float)(hh + k / 3 - 1) + offy;
        float px = (float)(ww + k % 3 - 1) + offx;
        float fy = floorf(py), fx = floorf(px);
        int y0 = (int)fy, x0 = (int)fx, y1 = y0 + 1, x1 = x0 + 1;
        float wy = py - fy, wx = px - fx;

        float my0 = (y0 >= 0 && y0 < HN) ? 1.f : 0.f;
        float my1 = (y1 >= 0 && y1 < HN) ? 1.f : 0.f;
        float mx0 = (x0 >= 0 && x0 < WN) ? 1.f : 0.f;
        float mx1 = (x1 >= 0 && x1 < WN) ? 1.f : 0.f;
        int y0c = min(max(y0, 0), HN - 1), y1c = min(max(y1, 0), HN - 1);
        int x0c = min(max(x0, 0), WN - 1), x1c = min(max(x1, 0), WN - 1);

        int yy[2] = { y0c, y1c };
        int xx[2] = { x0c, x1c };
        float wq[4] = { (1.f - wy) * (1.f - wx) * my0 * mx0,
                        (1.f - wy) * wx          * my0 * mx1,
                        wy * (1.f - wx)          * my1 * mx0,
                        wy * wx                  * my1 * mx1 };
        #pragma unroll
        for (int q = 0; q < 4; q++) {
            int yq = yy[q >> 1], xq = xx[q & 1];
            int ry = yq - (h - 2), rx = xq - (w0 - 2);
            int enc;
            if (ry >= 0 && ry < TR && rx >= 0 && rx < TC)
                enc = ry * TC + rx;                 // in-tile: >= 0
            else
                enc = ~(yq * WN + xq);              // global fallback: < 0
            s_i[q * 144 + p] = enc;
            s_w[q * 144 + p] = wq[q];
        }
    }
    __syncthreads();

    // Phase 2: 18 iters; half-warp = one kd-pair, 16 hw lanes.
    #pragma unroll 2
    for (int i = 0; i < 18; i++) {
        int qp  = i * 16 + (tid >> 4);
        int hwl = tid & 15;
        int kd0 = qp * 2;
        int c0 = kd0 / 9, k0 = kd0 - 9 * c0;
        int kd1 = kd0 + 1;
        int c1 = kd1 / 9, k1 = kd1 - 9 * c1;

        int pa = hwl * 9 + k0;
        int pb = hwl * 9 + k1;
        const float* t0 = s_x + c0 * CSTRIDE;
        const float* t1 = s_x + c1 * CSTRIDE;
        const float* xc0 = xg + (size_t)c0 * HW;
        const float* xc1 = xg + (size_t)c1 * HW;

        float v0 = 0.f, v1 = 0.f;
        #pragma unroll
        for (int q = 0; q < 4; q++) {
            int ea = s_i[q * 144 + pa];
            int eb = s_i[q * 144 + pb];
            float sa, sbv;
            if (ea >= 0) sa = t0[ea]; else sa = xc0[~ea];
            if (eb >= 0) sbv = t1[eb]; else sbv = xc1[~eb];
            v0 += s_w[q * 144 + pa] * sa;
            v1 += s_w[q * 144 + pb] * sbv;
        }

        __nv_bfloat16 h0 = __float2bfloat16(v0);
        __nv_bfloat16 l0 = __float2bfloat16(v0 - __bfloat162float(h0));
        __nv_bfloat16 h1 = __float2bfloat16(v1);
        __nv_bfloat16 l1 = __float2bfloat16(v1 - __bfloat162float(h1));

        uint32_t ph = ((uint32_t)__bfloat16_as_ushort(h1) << 16) |
                       (uint32_t)__bfloat16_as_ushort(h0);
        uint32_t pl = ((uint32_t)__bfloat16_as_ushort(l1) << 16) |
                       (uint32_t)__bfloat16_as_ushort(l0);
        s_h[hwl * SROW + qp] = ph;
        s_l[hwl * SROW + qp] = pl;
    }
    __syncthreads();

    // Phase 3: coalesced writeout, 288-word bursts per hw row.
    uint32_t* gh = (uint32_t*)(g_colh + ((size_t)b * HW) * KD + (size_t)g * 576);
    uint32_t* gl = (uint32_t*)(g_coll + ((size_t)b * HW) * KD + (size_t)g * 576);
    for (int idx = tid; idx < V4HW * QP; idx += 256) {
        int hwl = idx / QP;
        int q   = idx - hwl * QP;
        size_t goff = (size_t)(hw0 + hwl) * (KD / 2) + q;
        gh[goff] = s_h[hwl * SROW + q];
        gl[goff] = s_l[hwl * SROW + q];
    }
}

// ---------------------------------------------------------------------------
// Kernel C: mma.sync bf16 split GEMM, 128x128 tile, 512 threads.
// Per-warp math identical to validated version (warp covers 32x32:
// 2 mf x 4 nf). 3-stage cp.async pipeline, one __syncthreads per chunk.
// ---------------------------------------------------------------------------
__global__ void __launch_bounds__(512, 1)
gemm_mma_kernel(float* __restrict__ out)
{
    extern __shared__ char smem[];
    const uint32_t sb = smem_u32(smem);
    const int tid = threadIdx.x;
    const int wid = tid >> 5, lane = tid & 31;
    const int warp_m = wid & 3;          // 0..3
    const int warp_n = wid >> 2;         // 0..3
    const int m0 = blockIdx.x * BM;      // m fastest: both m-CTAs share B in L2
    const int n0 = blockIdx.y * BNT;
    const int b  = blockIdx.z;

    const __nv_bfloat16* Ah = g_wh + (size_t)m0 * KD;
    const __nv_bfloat16* Al = g_wl + (size_t)m0 * KD;
    const __nv_bfloat16* Bh = g_colh + ((size_t)(b * HW + n0)) * KD;
    const __nv_bfloat16* Bl = g_coll + ((size_t)(b * HW + n0)) * KD;

    // loader map: 512 16B-units per tile, one per thread
    const int lrow = tid >> 2, lcs = (tid & 3);

    float c[2][4][4];
    #pragma unroll
    for (int i = 0; i < 2; i++)
        #pragma unroll
        for (int j = 0; j < 4; j++)
            #pragma unroll
            for (int q = 0; q < 4; q++) c[i][j][q] = 0.f;

    auto load_chunk = [&](int ch, int stg) {
        const int k0 = ch * BK;
        uint32_t st = sb + stg * STAGE_B;
        cp16(st + 0 * T_A + lrow * ROWB + lcs * 16, Ah + (size_t)lrow * KD + k0 + lcs * 8);
        cp16(st + 1 * T_A + lrow * ROWB + lcs * 16, Al + (size_t)lrow * KD + k0 + lcs * 8);
        cp16(st + 2 * T_A + lrow * ROWB + lcs * 16, Bh + (size_t)lrow * KD + k0 + lcs * 8);
        cp16(st + 2 * T_A + T_B + lrow * ROWB + lcs * 16, Bl + (size_t)lrow * KD + k0 + lcs * 8);
        CP_COMMIT();
    };

    load_chunk(0, 0);

    for (int ch = 0; ch < NCH; ch++) {
        if (ch + 1 < NCH) {
            load_chunk(ch + 1, (ch + 1) % NSTAGE);
            CP_WAIT(1);
        } else {
            CP_WAIT(0);
        }
        __syncthreads();

        const uint32_t st = sb + (ch % NSTAGE) * STAGE_B;
        #pragma unroll
        for (int ks = 0; ks < 2; ks++) {
            uint32_t a_off = (uint32_t)((warp_m * 32 + (lane & 15)) * ROWB
                                        + ks * 32 + ((lane >> 4) << 4));
            uint32_t ah[2][4], al[2][4];
            #pragma unroll
            for (int mf = 0; mf < 2; mf++) {
                ldm_x4(ah[mf], st + 0 * T_A + a_off + mf * 16 * ROWB);
                ldm_x4(al[mf], st + 1 * T_A + a_off + mf * 16 * ROWB);
            }
            uint32_t b_off = (uint32_t)((warp_n * 32 + (lane & 7) + ((lane >> 4) << 3)) * ROWB
                                        + ks * 32 + (((lane >> 3) & 1) << 4));
            uint32_t bh[4][2], bl[4][2];
            #pragma unroll
            for (int nfp = 0; nfp < 2; nfp++) {
                uint32_t r[4];
                ldm_x4(r, st + 2 * T_A + b_off + nfp * 16 * ROWB);
                bh[nfp * 2][0] = r[0]; bh[nfp * 2][1] = r[1];
                bh[nfp * 2 + 1][0] = r[2]; bh[nfp * 2 + 1][1] = r[3];
                ldm_x4(r, st + 2 * T_A + T_B + b_off + nfp * 16 * ROWB);
                bl[nfp * 2][0] = r[0]; bl[nfp * 2][1] = r[1];
                bl[nfp * 2 + 1][0] = r[2]; bl[nfp * 2 + 1][1] = r[3];
            }
            #pragma unroll
            for (int mf = 0; mf < 2; mf++)
                #pragma unroll
                for (int nf = 0; nf < 4; nf++) {
                    mma_bf16(c[mf][nf], ah[mf], bh[nf]);
                    mma_bf16(c[mf][nf], ah[mf], bl[nf]);
                    mma_bf16(c[mf][nf], al[mf], bh[nf]);
                }
        }
    }

    #pragma unroll
    for (int mf = 0; mf < 2; mf++)
        #pragma unroll
        for (int nf = 0; nf < 4; nf++) {
            int row = m0 + warp_m * 32 + mf * 16 + (lane >> 2);
            int col = n0 + warp_n * 32 + nf * 8 + 2 * (lane & 3);
            float* op0 = out + ((size_t)(b * ON + row)) * HW + col;
            float* op1 = out + ((size_t)(b * ON + row + 8)) * HW + col;
            *(float2*)op0 = make_float2(c[mf][nf][0], c[mf][nf][1]);
            *(float2*)op1 = make_float2(c[mf][nf][2], c[mf][nf][3]);
        }
}

// ---------------------------------------------------------------------------
// GroupNorm stats + normalize (validated)
// ---------------------------------------------------------------------------
__global__ void gn_stats_kernel(const float* __restrict__ y)
{
    const int bg = blockIdx.x;
    const float* p = y + (size_t)bg * GRP_ELEMS;
    float s = 0.f, ss = 0.f;
    for (int i = threadIdx.x * 4; i < GRP_ELEMS; i += blockDim.x * 4) {
        float4 v = *(const float4*)(p + i);
        s  += v.x + v.y + v.z + v.w;
        ss += v.x * v.x + v.y * v.y + v.z * v.z + v.w * v.w;
    }
    #pragma unroll
    for (int off = 16; off > 0; off >>= 1) {
        s  += __shfl_down_sync(0xffffffffu, s,  off);
        ss += __shfl_down_sync(0xffffffffu, ss, off);
    }
    __shared__ float sh_s[8], sh_ss[8];
    int wid = threadIdx.x >> 5, lid = threadIdx.x & 31;
    if (lid == 0) { sh_s[wid] = s; sh_ss[wid] = ss; }
    __syncthreads();
    if (wid == 0) {
        s  = (lid < 8) ? sh_s[lid]  : 0.f;
        ss = (lid < 8) ? sh_ss[lid] : 0.f;
        #pragma unroll
        for (int off = 4; off > 0; off >>= 1) {
            s  += __shfl_down_sync(0xffffffffu, s,  off);
            ss += __shfl_down_sync(0xffffffffu, ss, off);
        }
        if (lid == 0) {
            float mu  = s * (1.f / GRP_ELEMS);
            float var = ss * (1.f / GRP_ELEMS) - mu * mu;
            g_mu[bg]   = mu;
            g_rstd[bg] = rsqrtf(var + EPS);
        }
    }
}

__global__ void gn_norm_kernel(float* __restrict__ y,
                               const float* __restrict__ gamma,
                               const float* __restrict__ beta)
{
    int idx = blockIdx.x * blockDim.x + threadIdx.x;
    int bg = idx >> 13;
    int c  = (idx >> 10) & 255;
    float mu = g_mu[bg];
    float r  = g_rstd[bg];
    float a  = r * gamma[c];
    float bb = beta[c] - mu * a;
    float4 v = *(float4*)(y + (size_t)idx * 4);
    v.x = fmaxf(fmaf(v.x, a, bb), 0.f);
    v.y = fmaxf(fmaf(v.y, a, bb), 0.f);
    v.z = fmaxf(fmaf(v.z, a, bb), 0.f);
    v.w = fmaxf(fmaf(v.w, a, bb), 0.f);
    *(float4*)(y + (size_t)idx * 4) = v;
}

// ---------------------------------------------------------------------------
// Launcher (full-batch)
// ---------------------------------------------------------------------------
extern "C" void kernel_launch(void* const* d_in, const int* in_sizes, int n_in,
                              void* d_out, int out_size)
{
    const float* x        = (const float*)d_in[0];
    const float* x_off    = (const float*)d_in[1];
    const float* w_offset = (const float*)d_in[2];
    const float* w_deform = (const float*)d_in[3];
    const float* gamma    = (const float*)d_in[4];
    const float* beta     = (const float*)d_in[5];
    float* out = (float*)d_out;

    cudaFuncSetAttribute(gemm_mma_kernel,
                         cudaFuncAttributeMaxDynamicSharedMemorySize,
                         GEMM_SMEM);
    cudaFuncSetAttribute(im2col4_kernel,
                         cudaFuncAttributeMaxDynamicSharedMemorySize,
                         IM2_SMEM);

    // 1) weight split
    wsplit_kernel<<<(ON * KD) / 256, 256>>>(w_deform);

    // 2) deformable im2col v4 (SMEM x-tile, global fallback)
    {
        dim3 gi(HW / V4HW, DGN, BN);         // (256, 4, 8)
        im2col4_kernel<<<gi, 256, IM2_SMEM>>>(x, x_off, w_offset);
    }

    // 3) tensor-core GEMM, 128x128 tiles
    {
        dim3 gg(ON / BM, HW / BNT, BN);      // (2, 32, 8)
        gemm_mma_kernel<<<gg, 512, GEMM_SMEM>>>(out);
    }

    // 4) GroupNorm
    gn_stats_kernel<<<BN * GN_GROUPS, 256>>>(out);
    gn_norm_kernel<<<(BN * ON * HW / 4) / 256, 256>>>(out, gamma, beta);
}

// round 13
// speedup vs baseline: 1.1169x; 1.1169x over previous
#include <cuda_runtime.h>
#include <cuda_bf16.h>
#include <stdint.h>
#include <math.h>

// Problem constants
#define BN 8
#define CN 256
#define ON 256
#define HN 64
#define WN 64
#define HW 4096
#define K2 9
#define DGN 4
#define CGN 64
#define KD 2304          // CN*K2 (GEMM reduction dim)
#define GN_GROUPS 32
#define GRP_ELEMS 32768
#define EPS 1e-5f

// GEMM tiling (128x64, 256 threads, 8 warps as 4m x 2n; per-warp 32x32)
#define BM 128
#define BNT 64
#define BK 32
#define NCH (KD / BK)        // 72
#define ROWB 80              // padded SMEM row stride (bytes) for 32 bf16
#define T_A (BM * ROWB)      // 10240
#define T_B (BNT * ROWB)     // 5120
#define STAGE_B (2 * T_A + 2 * T_B)   // 30720
#define NSTAGE 3
#define GEMM_SMEM (NSTAGE * STAGE_B)  // 92160

// ---------------------------------------------------------------------------
// Device scratch
// ---------------------------------------------------------------------------
__device__ __nv_bfloat16 g_colh[(size_t)BN * HW * KD];   // [b][hw][kd]
__device__ __nv_bfloat16 g_coll[(size_t)BN * HW * KD];
__device__ __nv_bfloat16 g_wh[(size_t)ON * KD];
__device__ __nv_bfloat16 g_wl[(size_t)ON * KD];
__device__ float g_mu[BN * GN_GROUPS];
__device__ float g_rstd[BN * GN_GROUPS];

// ---------------------------------------------------------------------------
// PTX helpers (stable sm_80+ features only)
// ---------------------------------------------------------------------------
__device__ __forceinline__ uint32_t smem_u32(const void* p) {
    uint32_t a;
    asm("{ .reg .u64 t; cvta.to.shared.u64 t, %1; cvt.u32.u64 %0, t; }"
        : "=r"(a) : "l"(p));
    return a;
}
__device__ __forceinline__ void cp16(uint32_t s, const void* g) {
    asm volatile("cp.async.cg.shared.global [%0], [%1], 16;"
                 :: "r"(s), "l"(g) : "memory");
}
#define CP_COMMIT() asm volatile("cp.async.commit_group;" ::: "memory")
#define CP_WAIT(n)  asm volatile("cp.async.wait_group %0;" :: "n"(n) : "memory")

__device__ __forceinline__ void ldm_x4(uint32_t* r, uint32_t addr) {
    asm volatile("ldmatrix.sync.aligned.m8n8.x4.shared.b16 {%0,%1,%2,%3}, [%4];"
                 : "=r"(r[0]), "=r"(r[1]), "=r"(r[2]), "=r"(r[3]) : "r"(addr));
}
__device__ __forceinline__ void mma_bf16(float* c, const uint32_t* a,
                                         const uint32_t* b) {
    asm volatile(
        "mma.sync.aligned.m16n8k16.row.col.f32.bf16.bf16.f32 "
        "{%0,%1,%2,%3}, {%4,%5,%6,%7}, {%8,%9}, {%0,%1,%2,%3};"
        : "+f"(c[0]), "+f"(c[1]), "+f"(c[2]), "+f"(c[3])
        : "r"(a[0]), "r"(a[1]), "r"(a[2]), "r"(a[3]), "r"(b[0]), "r"(b[1]));
}

// ---------------------------------------------------------------------------
// Kernel A: split weights into bf16 hi/lo.
// ---------------------------------------------------------------------------
__global__ void wsplit_kernel(const float* __restrict__ w)
{
    int i = blockIdx.x * blockDim.x + threadIdx.x;
    float v = w[i];
    __nv_bfloat16 h = __float2bfloat16(v);
    __nv_bfloat16 l = __float2bfloat16(v - __bfloat162float(h));
    g_wh[i] = h;
    g_wl[i] = l;
}

// ---------------------------------------------------------------------------
// Kernel B (v5): fused offset-projection + deformable im2col.
// Phase 1 / phase 3 identical to validated v3; phase 2 k-outer, c-inner so
// each thread's 8 bilinear params stay in registers for 4 channels.
// Output: col[b][hw][kd], kd = g*576 + c*9 + k, bf16 hi/lo.
// ---------------------------------------------------------------------------
#define V5HW 16
#define QP   288
#define SROW 289               // uint32 row stride (289 mod 32 == 1)
__global__ void __launch_bounds__(256)
im2col5_kernel(const float* __restrict__ x,
               const float* __restrict__ x_off,
               const float* __restrict__ w_offset)
{
    const int b   = blockIdx.z;
    const int g   = blockIdx.y;
    const int hw0 = blockIdx.x * V5HW;
    const int tid = threadIdx.x;

    __shared__ int      s_i[4][V5HW * 9];
    __shared__ float    s_w[4][V5HW * 9];
    __shared__ uint32_t s_h[V5HW * SROW];    // packed bf16x2 (kd even, kd odd)
    __shared__ uint32_t s_l[V5HW * SROW];

    // Phase 1: bilinear params for 16 hw x 9 k (validated math, unchanged)
    if (tid < V5HW * 9) {
        int p   = tid;
        int hwl = p / 9;
        int k   = p - hwl * 9;
        int hw  = hw0 + hwl;
        int h = hw >> 6, w = hw & 63;

        const float* xo = x_off + (size_t)b * 4 * HW + hw;
        float o0 = xo[0], o1 = xo[HW], o2 = xo[2 * HW], o3 = xo[3 * HW];
        const float* wo = w_offset + (size_t)((g * K2 + k) * 2) * 4;
        float offy = wo[0] * o0 + wo[1] * o1 + wo[2] * o2 + wo[3] * o3;
        float offx = wo[4] * o0 + wo[5] * o1 + wo[6] * o2 + wo[7] * o3;

        float py = (float)(h + k / 3 - 1) + offy;
        float px = (float)(w + k % 3 - 1) + offx;
        float fy = floorf(py), fx = floorf(px);
        int y0 = (int)fy, x0 = (int)fx, y1 = y0 + 1, x1 = x0 + 1;
        float wy = py - fy, wx = px - fx;

        float my0 = (y0 >= 0 && y0 < HN) ? 1.f : 0.f;
        float my1 = (y1 >= 0 && y1 < HN) ? 1.f : 0.f;
        float mx0 = (x0 >= 0 && x0 < WN) ? 1.f : 0.f;
        float mx1 = (x1 >= 0 && x1 < WN) ? 1.f : 0.f;
        int y0c = min(max(y0, 0), HN - 1), y1c = min(max(y1, 0), HN - 1);
        int x0c = min(max(x0, 0), WN - 1), x1c = min(max(x1, 0), WN - 1);

        s_i[0][p] = y0c * WN + x0c;
        s_i[1][p] = y0c * WN + x1c;
        s_i[2][p] = y1c * WN + x0c;
        s_i[3][p] = y1c * WN + x1c;
        s_w[0][p] = (1.f - wy) * (1.f - wx) * my0 * mx0;
        s_w[1][p] = (1.f - wy) * wx          * my0 * mx1;
        s_w[2][p] = wy * (1.f - wx)          * my1 * mx0;
        s_w[3][p] = wy * wx                  * my1 * mx1;
    }
    __syncthreads();

    const float* xg = x + ((size_t)(b * CN + g * CGN)) * HW;
    uint16_t* s_h16 = (uint16_t*)s_h;
    uint16_t* s_l16 = (uint16_t*)s_l;

    // Phase 2 (k-outer): thread = (hwl = tid&15, slot s = tid>>4).
    // For each k: load 8 params once, then 4 channels c = jj*16 + s.
    {
        const int hwl = tid & 15;
        const int s   = tid >> 4;
        const int p   = hwl * 9;           // base into param tables

        for (int k = 0; k < 9; k++) {
            int   i0 = s_i[0][p + k], i1 = s_i[1][p + k];
            int   i2 = s_i[2][p + k], i3 = s_i[3][p + k];
            float w0 = s_w[0][p + k], w1 = s_w[1][p + k];
            float w2 = s_w[2][p + k], w3 = s_w[3][p + k];

            #pragma unroll
            for (int jj = 0; jj < 4; jj++) {
                int c = jj * 16 + s;
                const float* xc = xg + (size_t)c * HW;
                float v = w0 * xc[i0] + w1 * xc[i1] +
                          w2 * xc[i2] + w3 * xc[i3];
                __nv_bfloat16 hb = __float2bfloat16(v);
                __nv_bfloat16 lb = __float2bfloat16(v - __bfloat162float(hb));
                int kd = c * 9 + k;
                s_h16[hwl * (SROW * 2) + kd] = __bfloat16_as_ushort(hb);
                s_l16[hwl * (SROW * 2) + kd] = __bfloat16_as_ushort(lb);
            }
        }
    }
    __syncthreads();

    // Phase 3: coalesced writeout, 288-word bursts per hw row (unchanged).
    uint32_t* gh = (uint32_t*)(g_colh + ((size_t)b * HW) * KD + (size_t)g * 576);
    uint32_t* gl = (uint32_t*)(g_coll + ((size_t)b * HW) * KD + (size_t)g * 576);
    for (int idx = tid; idx < V5HW * QP; idx += 256) {
        int hwl = idx / QP;
        int q   = idx - hwl * QP;
        size_t goff = (size_t)(hw0 + hwl) * (KD / 2) + q;
        gh[goff] = s_h[hwl * SROW + q];
        gl[goff] = s_l[hwl * SROW + q];
    }
}

// ---------------------------------------------------------------------------
// Kernel C: mma.sync bf16 split GEMM. 3-stage cp.async pipeline with the
// RACE-FREE ordering: wait -> barrier -> issue -> compute. The overwrite of
// stage (ch-1)%3 is issued only after the barrier that every warp reaches
// only once it has finished reading that stage in iteration ch-1.
// ---------------------------------------------------------------------------
__global__ void __launch_bounds__(256, 2)
gemm_mma_kernel(float* __restrict__ out)
{
    extern __shared__ char smem[];
    const uint32_t sb = smem_u32(smem);
    const int tid = threadIdx.x;
    const int wid = tid >> 5, lane = tid & 31;
    const int warp_m = wid & 3;
    const int warp_n = wid >> 2;
    const int m0 = blockIdx.x * BM;
    const int n0 = blockIdx.y * BNT;
    const int b  = blockIdx.z;

    const __nv_bfloat16* Ah = g_wh + (size_t)m0 * KD;
    const __nv_bfloat16* Al = g_wl + (size_t)m0 * KD;
    const __nv_bfloat16* Bh = g_colh + ((size_t)(b * HW + n0)) * KD;
    const __nv_bfloat16* Bl = g_coll + ((size_t)(b * HW + n0)) * KD;

    const int arow0 = tid >> 2,         acs0 = (tid & 3);
    const int arow1 = (tid + 256) >> 2, acs1 = (tid & 3);
    const int brow = tid >> 2, bcs = (tid & 3);

    float c[2][4][4];
    #pragma unroll
    for (int i = 0; i < 2; i++)
        #pragma unroll
        for (int j = 0; j < 4; j++)
            #pragma unroll
            for (int q = 0; q < 4; q++) c[i][j][q] = 0.f;

    auto load_chunk = [&](int ch, int stg) {
        const int k0 = ch * BK;
        uint32_t st = sb + stg * STAGE_B;
        cp16(st + 0 * T_A + arow0 * ROWB + acs0 * 16, Ah + (size_t)arow0 * KD + k0 + acs0 * 8);
        cp16(st + 0 * T_A + arow1 * ROWB + acs1 * 16, Ah + (size_t)arow1 * KD + k0 + acs1 * 8);
        cp16(st + 1 * T_A + arow0 * ROWB + acs0 * 16, Al + (size_t)arow0 * KD + k0 + acs0 * 8);
        cp16(st + 1 * T_A + arow1 * ROWB + acs1 * 16, Al + (size_t)arow1 * KD + k0 + acs1 * 8);
        cp16(st + 2 * T_A + brow * ROWB + bcs * 16,   Bh + (size_t)brow * KD + k0 + bcs * 8);
        cp16(st + 2 * T_A + T_B + brow * ROWB + bcs * 16, Bl + (size_t)brow * KD + k0 + bcs * 8);
        CP_COMMIT();
    };

    // Prologue: chunks 0 and 1 into stages 0 and 1.
    load_chunk(0, 0);
    load_chunk(1, 1);

    for (int ch = 0; ch < NCH; ch++) {
        // 1) ensure this iteration's stage (group ch) has landed
        if (ch + 1 < NCH) {
            CP_WAIT(1);
        } else {
            CP_WAIT(0);
        }
        // 2) barrier: all warps are done with iteration ch-1's stage
        __syncthreads();
        // 3) only now overwrite stage (ch+2)%3 == (ch-1)%3
        if (ch + 2 < NCH) {
            load_chunk(ch + 2, (ch + 2) % NSTAGE);
        }

        // 4) compute on stage ch%3
        const uint32_t st = sb + (ch % NSTAGE) * STAGE_B;
        #pragma unroll
        for (int ks = 0; ks < 2; ks++) {
            uint32_t a_off = (uint32_t)((warp_m * 32 + (lane & 15)) * ROWB
                                        + ks * 32 + ((lane >> 4) << 4));
            uint32_t ah[2][4], al[2][4];
            #pragma unroll
            for (int mf = 0; mf < 2; mf++) {
                ldm_x4(ah[mf], st + 0 * T_A + a_off + mf * 16 * ROWB);
                ldm_x4(al[mf], st + 1 * T_A + a_off + mf * 16 * ROWB);
            }
            uint32_t b_off = (uint32_t)((warp_n * 32 + (lane & 7) + ((lane >> 4) << 3)) * ROWB
                                        + ks * 32 + (((lane >> 3) & 1) << 4));
            uint32_t bh[4][2], bl[4][2];
            #pragma unroll
            for (int nfp = 0; nfp < 2; nfp++) {
                uint32_t r[4];
                ldm_x4(r, st + 2 * T_A + b_off + nfp * 16 * ROWB);
                bh[nfp * 2][0] = r[0]; bh[nfp * 2][1] = r[1];
                bh[nfp * 2 + 1][0] = r[2]; bh[nfp * 2 + 1][1] = r[3];
                ldm_x4(r, st + 2 * T_A + T_B + b_off + nfp * 16 * ROWB);
                bl[nfp * 2][0] = r[0]; bl[nfp * 2][1] = r[1];
                bl[nfp * 2 + 1][0] = r[2]; bl[nfp * 2 + 1][1] = r[3];
            }
            #pragma unroll
            for (int mf = 0; mf < 2; mf++)
                #pragma unroll
                for (int nf = 0; nf < 4; nf++) {
                    mma_bf16(c[mf][nf], ah[mf], bh[nf]);
                    mma_bf16(c[mf][nf], ah[mf], bl[nf]);
                    mma_bf16(c[mf][nf], al[mf], bh[nf]);
                }
        }
    }

    #pragma unroll
    for (int mf = 0; mf < 2; mf++)
        #pragma unroll
        for (int nf = 0; nf < 4; nf++) {
            int row = m0 + warp_m * 32 + mf * 16 + (lane >> 2);
            int col = n0 + warp_n * 32 + nf * 8 + 2 * (lane & 3);
            float* op0 = out + ((size_t)(b * ON + row)) * HW + col;
            float* op1 = out + ((size_t)(b * ON + row + 8)) * HW + col;
            *(float2*)op0 = make_float2(c[mf][nf][0], c[mf][nf][1]);
            *(float2*)op1 = make_float2(c[mf][nf][2], c[mf][nf][3]);
        }
}

// ---------------------------------------------------------------------------
// GroupNorm stats + normalize (validated)
// ---------------------------------------------------------------------------
__global__ void gn_stats_kernel(const float* __restrict__ y)
{
    const int bg = blockIdx.x;
    const float* p = y + (size_t)bg * GRP_ELEMS;
    float s = 0.f, ss = 0.f;
    for (int i = threadIdx.x * 4; i < GRP_ELEMS; i += blockDim.x * 4) {
        float4 v = *(const float4*)(p + i);
        s  += v.x + v.y + v.z + v.w;
        ss += v.x * v.x + v.y * v.y + v.z * v.z + v.w * v.w;
    }
    #pragma unroll
    for (int off = 16; off > 0; off >>= 1) {
        s  += __shfl_down_sync(0xffffffffu, s,  off);
        ss += __shfl_down_sync(0xffffffffu, ss, off);
    }
    __shared__ float sh_s[8], sh_ss[8];
    int wid = threadIdx.x >> 5, lid = threadIdx.x & 31;
    if (lid == 0) { sh_s[wid] = s; sh_ss[wid] = ss; }
    __syncthreads();
    if (wid == 0) {
        s  = (lid < 8) ? sh_s[lid]  : 0.f;
        ss = (lid < 8) ? sh_ss[lid] : 0.f;
        #pragma unroll
        for (int off = 4; off > 0; off >>= 1) {
            s  += __shfl_down_sync(0xffffffffu, s,  off);
            ss += __shfl_down_sync(0xffffffffu, ss, off);
        }
        if (lid == 0) {
            float mu  = s * (1.f / GRP_ELEMS);
            float var = ss * (1.f / GRP_ELEMS) - mu * mu;
            g_mu[bg]   = mu;
            g_rstd[bg] = rsqrtf(var + EPS);
        }
    }
}

__global__ void gn_norm_kernel(float* __restrict__ y,
                               const float* __restrict__ gamma,
                               const float* __restrict__ beta)
{
    int idx = blockIdx.x * blockDim.x + threadIdx.x;
    int bg = idx >> 13;
    int c  = (idx >> 10) & 255;
    float mu = g_mu[bg];
    float r  = g_rstd[bg];
    float a  = r * gamma[c];
    float bb = beta[c] - mu * a;
    float4 v = *(float4*)(y + (size_t)idx * 4);
    v.x = fmaxf(fmaf(v.x, a, bb), 0.f);
    v.y = fmaxf(fmaf(v.y, a, bb), 0.f);
    v.z = fmaxf(fmaf(v.z, a, bb), 0.f);
    v.w = fmaxf(fmaf(v.w, a, bb), 0.f);
    *(float4*)(y + (size_t)idx * 4) = v;
}

// ---------------------------------------------------------------------------
// Launcher (full-batch)
// ---------------------------------------------------------------------------
extern "C" void kernel_launch(void* const* d_in, const int* in_sizes, int n_in,
                              void* d_out, int out_size)
{
    const float* x        = (const float*)d_in[0];
    const float* x_off    = (const float*)d_in[1];
    const float* w_offset = (const float*)d_in[2];
    const float* w_deform = (const float*)d_in[3];
    const float* gamma    = (const float*)d_in[4];
    const float* beta     = (const float*)d_in[5];
    float* out = (float*)d_out;

    cudaFuncSetAttribute(gemm_mma_kernel,
                         cudaFuncAttributeMaxDynamicSharedMemorySize,
                         GEMM_SMEM);

    // 1) weight split
    wsplit_kernel<<<(ON * KD) / 256, 256>>>(w_deform);

    // 2) deformable im2col v5 (k-outer phase 2)
    {
        dim3 gi(HW / V5HW, DGN, BN);         // (256, 4, 8)
        im2col5_kernel<<<gi, 256>>>(x, x_off, w_offset);
    }

    // 3) tensor-core GEMM (race-free 3-stage, m-tiles fastest for B L2 reuse)
    {
        dim3 gg(ON / BM, HW / BNT, BN);      // (2, 64, 8)
        gemm_mma_kernel<<<gg, 256, GEMM_SMEM>>>(out);
    }

    // 4) GroupNorm
    gn_stats_kernel<<<BN * GN_GROUPS, 256>>>(out);
    gn_norm_kernel<<<(BN * ON * HW / 4) / 256, 256>>>(out, gamma, beta);
}